// round 8
// baseline (speedup 1.0000x reference)
#include <cuda_runtime.h>
#include <math.h>

// Shapes (fixed by the problem)
#define HH   51          // hidden size
#define G4   204         // 4*H gate count
#define GP   208         // gates padded to multiple of 4
#define K1   52          // layer-1 K (H padded)
#define K2   104         // layer-2 K (2H padded: [h1 pad][h2 pad])
#define NSEQ 16          // sequences per block
#define NT   416         // threads per block (13 warps; 104 gate-pairs x 4 seq-quads)
#define NBLK 128         // 2048 / 16
#define TSZ  2048
#define XCH  64          // input/output staging chunk (timesteps)
#define GST  216         // gate-buffer row stride (floats), conflict-reducing pad

// shared layout (floats)
#define OFF_W1  0                       // [K1][GP]
#define OFF_W2  (OFF_W1 + K1*GP)        // [K2][GP]
#define OFF_ST  (OFF_W2 + K2*GP)        // [K2][16] transposed state: rows 0..51 h1, 52..103 h2
#define OFF_G   (OFF_ST + K2*16)        // [16][GST] gate pre-activations
#define OFF_X   (OFF_G  + NSEQ*GST)     // [16][XCH]
#define OFF_Y   (OFF_X  + NSEQ*XCH)     // [16][XCH]
#define OFF_B1  (OFF_Y  + NSEQ*XCH)     // [GP] b_ih1+b_hh1
#define OFF_B2  (OFF_B1 + GP)           // [GP] b_ih2+b_hh2
#define OFF_WI  (OFF_B2 + GP)           // [GP] W_ih1 (input weight column)
#define OFF_WL  (OFF_WI + GP)           // [52]: [0..50]=W_lin, [51]=b_lin
#define SMEM_FLOATS (OFF_WL + 52)

__device__ __forceinline__ float fsig(float x) {
    // 1/(1+exp(-x)); clamp exp arg so __fdividef never sees inf
    float e = __expf(fminf(-x, 80.f));
    return __fdividef(1.f, 1.f + e);
}
__device__ __forceinline__ float ftanh_f(float x) {
    float ax = fabsf(x);
    float e  = __expf(-2.f * ax);          // in (0,1], never overflows
    float t  = __fdividef(1.f - e, 1.f + e);
    return x >= 0.f ? t : -t;
}

__global__ __launch_bounds__(NT, 1)
void lstm2_kernel(const float* __restrict__ in,
                  const float* __restrict__ W_ih1,
                  const float* __restrict__ W_hh1,
                  const float* __restrict__ b_ih1,
                  const float* __restrict__ b_hh1,
                  const float* __restrict__ W_ih2,
                  const float* __restrict__ W_hh2,
                  const float* __restrict__ b_ih2,
                  const float* __restrict__ b_hh2,
                  const float* __restrict__ W_lin,
                  const float* __restrict__ b_lin,
                  float* __restrict__ out)
{
    extern __shared__ float sm[];
    float* sW1 = sm + OFF_W1;
    float* sW2 = sm + OFF_W2;
    float* sSt = sm + OFF_ST;
    float* sG  = sm + OFF_G;
    float* sX  = sm + OFF_X;
    float* sY  = sm + OFF_Y;
    float* sB1 = sm + OFF_B1;
    float* sB2 = sm + OFF_B2;
    float* sWi = sm + OFF_WI;
    float* sWl = sm + OFF_WL;

    const int tid  = threadIdx.x;
    const int seq0 = blockIdx.x * NSEQ;

    // ---- one-time loads: k-major padded weights ----
    for (int i = tid; i < K1*GP; i += NT) {
        int k = i / GP, g = i % GP;
        sW1[i] = (k < HH && g < G4) ? W_hh1[g*HH + k] : 0.f;
    }
    for (int i = tid; i < K2*GP; i += NT) {
        int k = i / GP, g = i % GP;
        float v = 0.f;
        if (g < G4) {
            if (k < HH)                    v = W_ih2[g*HH + k];        // input = h1
            else if (k >= K1 && k < K1+HH) v = W_hh2[g*HH + (k - K1)]; // recurrent h2
        }
        sW2[i] = v;
    }
    for (int i = tid; i < GP; i += NT) {
        sB1[i] = (i < G4) ? b_ih1[i] + b_hh1[i] : 0.f;
        sB2[i] = (i < G4) ? b_ih2[i] + b_hh2[i] : 0.f;
        sWi[i] = (i < G4) ? W_ih1[i] : 0.f;
    }
    for (int i = tid; i < 52; i += NT)
        sWl[i] = (i < HH) ? W_lin[i] : b_lin[0];   // [51] carries b_lin
    for (int i = tid; i < K2*16; i += NT) sSt[i] = 0.f;   // rows 51,103 stay 0 forever

    // ---- per-thread tile mapping: G=2 gates x S=4 seqs ----
    const int col  = tid % 104;       // gate-pair index
    const int srow = tid / 104;       // 0..3
    const int g0   = col * 2;
    const int s0   = srow * 4;

    // ---- activation-phase mapping: 2 (hidden,seq) items per thread, fixed -> c in regs
    float c1[2] = {0.f, 0.f}, c2[2] = {0.f, 0.f};

    for (int t = 0; t < TSZ; t++) {
        const int tin = t & (XCH - 1);
        if (tin == 0) {
            __syncthreads();                       // sY complete / weights ready (t==0)
            if (t) {
                const int tp = t - XCH;            // flush previous output chunk (coalesced)
                for (int i = tid; i < NSEQ*XCH; i += NT) {
                    int s = i >> 6, j = i & (XCH-1);
                    out[(size_t)(seq0 + s) * TSZ + tp + j] = sY[i];
                }
            }
            for (int i = tid; i < NSEQ*XCH; i += NT) {  // prefetch input chunk
                int s = i >> 6, j = i & (XCH-1);
                sX[i] = in[(size_t)(seq0 + s) * TSZ + t + j];
            }
            __syncthreads();
        }

        // ================= Phase A: layer-1 matvec =================
        {
            float acc[8] = {0,0,0,0,0,0,0,0};   // acc[gi*4+si]
            #pragma unroll 4
            for (int k = 0; k < K1; k++) {
                const float2 w = *(const float2*)(sW1 + k*GP + g0);   // contiguous, no conflict
                const float4 h = *(const float4*)(sSt + (k<<4) + s0); // broadcast
                acc[0] += w.x*h.x; acc[1] += w.x*h.y; acc[2] += w.x*h.z; acc[3] += w.x*h.w;
                acc[4] += w.y*h.x; acc[5] += w.y*h.y; acc[6] += w.y*h.z; acc[7] += w.y*h.w;
            }
            const float2 b  = *(const float2*)(sB1 + g0);
            const float2 wi = *(const float2*)(sWi + g0);
            #pragma unroll
            for (int si = 0; si < 4; si++) {
                int s = s0 + si;
                float x = sX[s*XCH + tin];
                float2 o;
                o.x = acc[si]     + b.x + wi.x * x;
                o.y = acc[4 + si] + b.y + wi.y * x;
                *(float2*)(sG + s*GST + g0) = o;
            }
        }
        __syncthreads();

        // ================= Phase B: layer-1 activations =================
        #pragma unroll
        for (int r = 0; r < 2; r++) {
            int id = tid + r*NT;
            if (id < HH*NSEQ) {
                int h = id >> 4, s = id & 15;
                const float* gr = sG + s*GST;
                float ig = gr[h], fg = gr[HH + h], gg = gr[2*HH + h], og = gr[3*HH + h];
                float cn = fsig(fg)*c1[r] + fsig(ig)*ftanh_f(gg);
                c1[r] = cn;
                sSt[(h<<4) + s] = fsig(og)*ftanh_f(cn);   // h1 -> state rows 0..50
            }
        }
        __syncthreads();

        // ================= Phase C: layer-2 matvec (K=104 over [h1;h2]) =================
        {
            float acc[8] = {0,0,0,0,0,0,0,0};
            #pragma unroll 4
            for (int k = 0; k < K2; k++) {
                const float2 w = *(const float2*)(sW2 + k*GP + g0);
                const float4 h = *(const float4*)(sSt + (k<<4) + s0);
                acc[0] += w.x*h.x; acc[1] += w.x*h.y; acc[2] += w.x*h.z; acc[3] += w.x*h.w;
                acc[4] += w.y*h.x; acc[5] += w.y*h.y; acc[6] += w.y*h.z; acc[7] += w.y*h.w;
            }
            const float2 b = *(const float2*)(sB2 + g0);
            #pragma unroll
            for (int si = 0; si < 4; si++) {
                int s = s0 + si;
                float2 o;
                o.x = acc[si]     + b.x;
                o.y = acc[4 + si] + b.y;
                *(float2*)(sG + s*GST + g0) = o;
            }
        }
        __syncthreads();

        // ================= Phase D: layer-2 activations =================
        #pragma unroll
        for (int r = 0; r < 2; r++) {
            int id = tid + r*NT;
            if (id < HH*NSEQ) {
                int h = id >> 4, s = id & 15;
                const float* gr = sG + s*GST;
                float ig = gr[h], fg = gr[HH + h], gg = gr[2*HH + h], og = gr[3*HH + h];
                float cn = fsig(fg)*c2[r] + fsig(ig)*ftanh_f(gg);
                c2[r] = cn;
                sSt[((K1 + h)<<4) + s] = fsig(og)*ftanh_f(cn);  // h2 -> state rows 52..102
            }
        }
        __syncthreads();

        // ================= Output: y = h2 . W_lin + b_lin (overlaps next Phase A) =========
        if (tid < 64) {
            int s = tid >> 2, p = tid & 3;
            float acc = 0.f;
            #pragma unroll
            for (int k = p; k < HH; k += 4)
                acc += sSt[((K1 + k)<<4) + s] * sWl[k];
            acc += __shfl_xor_sync(0xffffffffu, acc, 1);
            acc += __shfl_xor_sync(0xffffffffu, acc, 2);
            if (p == 0) sY[s*XCH + tin] = acc + sWl[HH];   // sWl[51] = b_lin
        }
        // no sync needed here: writers/readers of sY resolve at the chunk-boundary sync,
        // and next Phase A touches only sG/sSt[0..51]/sW1/sX (disjoint from this phase's reads)
    }

    // flush last output chunk
    __syncthreads();
    {
        const int tp = TSZ - XCH;
        for (int i = tid; i < NSEQ*XCH; i += NT) {
            int s = i >> 6, j = i & (XCH-1);
            out[(size_t)(seq0 + s) * TSZ + tp + j] = sY[i];
        }
    }
}

extern "C" void kernel_launch(void* const* d_in, const int* in_sizes, int n_in,
                              void* d_out, int out_size) {
    (void)in_sizes; (void)n_in; (void)out_size;
    const float* in    = (const float*)d_in[0];
    const float* W_ih1 = (const float*)d_in[1];
    const float* W_hh1 = (const float*)d_in[2];
    const float* b_ih1 = (const float*)d_in[3];
    const float* b_hh1 = (const float*)d_in[4];
    const float* W_ih2 = (const float*)d_in[5];
    const float* W_hh2 = (const float*)d_in[6];
    const float* b_ih2 = (const float*)d_in[7];
    const float* b_hh2 = (const float*)d_in[8];
    const float* W_lin = (const float*)d_in[9];
    const float* b_lin = (const float*)d_in[10];
    float* out = (float*)d_out;

    const size_t smem = (size_t)SMEM_FLOATS * sizeof(float);  // ~161 KB
    cudaFuncSetAttribute(lstm2_kernel,
                         cudaFuncAttributeMaxDynamicSharedMemorySize, (int)smem);
    lstm2_kernel<<<NBLK, NT, smem>>>(in, W_ih1, W_hh1, b_ih1, b_hh1,
                                     W_ih2, W_hh2, b_ih2, b_hh2,
                                     W_lin, b_lin, out);
}